// round 8
// baseline (speedup 1.0000x reference)
#include <cuda_runtime.h>
#include <cuda_fp16.h>
#include <stdint.h>

// ---------------- problem constants ----------------
namespace {
constexpr int T_  = 4096;
constexpr int D_  = 1024;
constexpr int E_  = 8;
constexpr int F_  = 2816;
constexpr int NP  = T_ * 2;       // 8192 (token,k) pairs
constexpr int N1  = 2 * F_;       // 5632
constexpr int BM  = 128;
constexpr int MAXTILES = 72;

// smem: per k32-chunk buffer, 3 planes (Ah, Al, Bh) of 128x32 fp16 = 8KB each
constexpr int PL   = 8192;
constexpr int BUF  = 3 * PL;          // 24576 per buffer
constexpr int NBUF = 3;
constexpr int SMEM_DYN = NBUF * BUF;  // 73728 (>= G2 staging 128*132*4 = 67584)

// prep region sizes (in float4 units)
constexpr int N4_X   = T_ * D_ / 4;                         // 1,048,576
constexpr int N4_GUP = (int)((size_t)E_ * N1 * D_ / 4);     // 11,534,336
constexpr int N4_DWN = (int)((size_t)E_ * D_ * F_ / 4);     // 5,767,168
constexpr int N4_OUT = T_ * D_ / 4;                         // 1,048,576
constexpr int N4_G1  = N4_X + N4_GUP;
constexpr int N4_G2  = N4_DWN + N4_OUT;
}

// ---------------- device scratch (static, allocation-free) ----------------
__device__ __align__(16) __half g_x_hi[(size_t)T_ * D_];
__device__ __align__(16) __half g_x_lo[(size_t)T_ * D_];
__device__ __align__(16) __half g_gup_hi[(size_t)E_ * N1 * D_];
__device__ __align__(16) __half g_dwn_hi[(size_t)E_ * D_ * F_];
__device__ __align__(16) __half g_act_hi[(size_t)NP * F_];
__device__ __align__(16) __half g_act_lo[(size_t)NP * F_];

__device__ int g_rowtok[NP];
__device__ int g_rowpair[NP];
__device__ int g_tile_e[MAXTILES];
__device__ int g_tile_r0[MAXTILES];
__device__ int g_tile_rows[MAXTILES];
__device__ int g_ntiles;

// ---------------- helpers ----------------
__device__ __forceinline__ uint32_t smem_u32(const void* p) {
    uint32_t a;
    asm("{ .reg .u64 t; cvta.to.shared.u64 t, %1; cvt.u32.u64 %0, t; }" : "=r"(a) : "l"(p));
    return a;
}
// fp16 hi/lo split of float4: hi = rn(v), lo = rn(v - float(hi))
__device__ __forceinline__ void split4h(float4 v, uint32_t& h0, uint32_t& h1,
                                        uint32_t& l0, uint32_t& l1) {
    __half2 H0 = __floats2half2_rn(v.x, v.y);
    __half2 H1 = __floats2half2_rn(v.z, v.w);
    float2 f0 = __half22float2(H0);
    float2 f1 = __half22float2(H1);
    __half2 L0 = __floats2half2_rn(v.x - f0.x, v.y - f0.y);
    __half2 L1 = __floats2half2_rn(v.z - f1.x, v.w - f1.y);
    h0 = *(uint32_t*)&H0; h1 = *(uint32_t*)&H1;
    l0 = *(uint32_t*)&L0; l1 = *(uint32_t*)&L1;
}
__device__ __forceinline__ void hi4h(float4 v, uint32_t& h0, uint32_t& h1) {
    __half2 H0 = __floats2half2_rn(v.x, v.y);
    __half2 H1 = __floats2half2_rn(v.z, v.w);
    h0 = *(uint32_t*)&H0; h1 = *(uint32_t*)&H1;
}
__device__ __forceinline__ void ldsm4(uint32_t& r0, uint32_t& r1, uint32_t& r2, uint32_t& r3,
                                      uint32_t addr) {
    asm volatile("ldmatrix.sync.aligned.m8n8.x4.shared.b16 {%0,%1,%2,%3}, [%4];"
                 : "=r"(r0), "=r"(r1), "=r"(r2), "=r"(r3) : "r"(addr));
}
__device__ __forceinline__ void mma16816(float* c, const uint32_t* a, uint32_t b0, uint32_t b1) {
    asm volatile(
        "mma.sync.aligned.m16n8k16.row.col.f32.f16.f16.f32 "
        "{%0,%1,%2,%3}, {%4,%5,%6,%7}, {%8,%9}, {%0,%1,%2,%3};"
        : "+f"(c[0]), "+f"(c[1]), "+f"(c[2]), "+f"(c[3])
        : "r"(a[0]), "r"(a[1]), "r"(a[2]), "r"(a[3]), "r"(b0), "r"(b1));
}
__device__ __forceinline__ void cp_async16(uint32_t dst, const void* src, int sz) {
    asm volatile("cp.async.cg.shared.global [%0], [%1], 16, %2;"
                 :: "r"(dst), "l"(src), "r"(sz) : "memory");
}
__device__ __forceinline__ void cp_commit() {
    asm volatile("cp.async.commit_group;" ::: "memory");
}
__device__ __forceinline__ void cp_wait0() {
    asm volatile("cp.async.wait_group 0;" ::: "memory");
}
__device__ __forceinline__ void cp_wait1() {
    asm volatile("cp.async.wait_group 1;" ::: "memory");
}
__device__ __forceinline__ void redadd(float* p, float v) {
    asm volatile("red.global.add.f32 [%0], %1;" :: "l"(p), "f"(v) : "memory");
}

// ---------------- merged single-block routing ----------------
// 1024 threads: assign slots (shared atomics), prefix over E=8, tiles, row maps.
__global__ void k_route(const int* __restrict__ ids) {
    __shared__ int scnt[E_];
    __shared__ int soff[E_ + 1];
    __shared__ int s_e[NP > 0 ? 1 : 1]; // placeholder (unused)
    const int tid = threadIdx.x;

    if (tid < E_) scnt[tid] = 0;
    __syncthreads();

    int pe[NP / 1024], ps[NP / 1024];
#pragma unroll
    for (int t = 0; t < NP / 1024; t++) {
        int p = tid + t * 1024;
        int e = ids[p];
        e = e < 0 ? 0 : (e >= E_ ? E_ - 1 : e);
        pe[t] = e;
        ps[t] = atomicAdd(&scnt[e], 1);
    }
    __syncthreads();

    if (tid == 0) {
        int off = 0;
        soff[0] = 0;
        for (int e = 0; e < E_; e++) { off += scnt[e]; soff[e + 1] = off; }
        int nt = 0;
        for (int e = 0; e < E_; e++)
            for (int r0 = soff[e]; r0 < soff[e + 1]; r0 += BM) {
                g_tile_e[nt] = e; g_tile_r0[nt] = r0;
                int rem = soff[e + 1] - r0;
                g_tile_rows[nt] = rem < BM ? rem : BM;
                nt++;
            }
        g_ntiles = nt;
    }
    __syncthreads();

#pragma unroll
    for (int t = 0; t < NP / 1024; t++) {
        int p = tid + t * 1024;
        int gr = soff[pe[t]] + ps[t];
        g_rowtok[gr]  = p >> 1;
        g_rowpair[gr] = p;
    }
}

// ---------------- prep kernels ----------------
// G1 deps: x split (hi+lo) + gup hi
__global__ void k_prep_g1(const float4* __restrict__ x, const float4* __restrict__ gup) {
    int i = blockIdx.x * 256 + threadIdx.x;
    if (i < N4_X) {
        float4 v = x[i];
        uint32_t h0, h1, l0, l1;
        split4h(v, h0, h1, l0, l1);
        ((uint2*)g_x_hi)[i] = make_uint2(h0, h1);
        ((uint2*)g_x_lo)[i] = make_uint2(l0, l1);
        return;
    }
    i -= N4_X;
    if (i < N4_GUP) {
        float4 v = gup[i];
        uint32_t h0, h1;
        hi4h(v, h0, h1);
        ((uint2*)g_gup_hi)[i] = make_uint2(h0, h1);
    }
}
// G2 deps: down hi + out zeroing (runs on forked stream, overlapped with G1)
__global__ void k_prep_g2(const float4* __restrict__ dwn, float4* __restrict__ out) {
    int i = blockIdx.x * 256 + threadIdx.x;
    if (i < N4_DWN) {
        float4 v = dwn[i];
        uint32_t h0, h1;
        hi4h(v, h0, h1);
        ((uint2*)g_dwn_hi)[i] = make_uint2(h0, h1);
        return;
    }
    i -= N4_DWN;
    if (i < N4_OUT) out[i] = make_float4(0.f, 0.f, 0.f, 0.f);
}

// ---------------- 2-product fp16 HMMA grouped GEMM (3-stage cp.async) ----------------
// D = Ahi.Bhi + Alo.Bhi   (B fp16-rounded; dropped A.Blo ~ 2^-12 rel)
// G1: act[row, j] = silu(x_row . gup[e, j, :]) * (x_row . gup[e, F+j, :])
//     block covers 64 j; B rows interleaved (2j = gate, 2j+1 = up)  KDIM=1024
// G2: out[tok, n] += w_pair * (act_row . down[e, n, :])  (N tile 128) KDIM=2816
template <bool G1>
__global__ void __launch_bounds__(256, 2)
moe_gemm_mma(const float* __restrict__ tw, float* __restrict__ outp) {
    constexpr int KDIM = G1 ? D_ : F_;
    constexpr int NC   = KDIM / 32;

    const int bt = blockIdx.y;
    if (bt >= g_ntiles) return;

    const int e    = g_tile_e[bt];
    const int row0 = g_tile_r0[bt];
    const int rows = g_tile_rows[bt];
    const int bn0  = blockIdx.x * (G1 ? 64 : 128);

    const __half* __restrict__ Ah = G1 ? g_x_hi : g_act_hi;
    const __half* __restrict__ Al = G1 ? g_x_lo : g_act_lo;
    const size_t eoff = (size_t)e * (G1 ? (size_t)N1 * D_ : (size_t)D_ * F_);
    const __half* __restrict__ Bh = (G1 ? g_gup_hi : g_dwn_hi) + eoff;

    extern __shared__ __align__(16) char dynraw[];
    const uint32_t dynbase = smem_u32(dynraw);

    __shared__ int   s_map[BM];
    __shared__ int   s_out[BM];
    __shared__ float s_wt[BM];

    const int tid  = threadIdx.x;
    const int wid  = tid >> 5;
    const int lane = tid & 31;

    if (tid < BM) {
        int amap = -1, omap = -1;
        float w = 0.f;
        if (tid < rows) {
            if (G1) { amap = g_rowtok[row0 + tid]; omap = row0 + tid; }
            else    { amap = row0 + tid;           omap = g_rowpair[row0 + tid];
                      w = tw[omap]; }
        }
        s_map[tid] = amap; s_out[tid] = omap; s_wt[tid] = w;
    }
    __syncthreads();

    // per-thread cp.async assignments (2 A row-units, 2 B row-units)
    const int rA0 = tid >> 2,         qA0 = tid & 3;
    const int rA1 = (tid + 256) >> 2, qA1 = tid & 3;

    auto issue = [&](int c) {
        const uint32_t base = dynbase + (uint32_t)(c % NBUF) * BUF;
        const int kofs = c * 32;
        {
            int ar = s_map[rA0];
            int sz = ar >= 0 ? 16 : 0;
            size_t so = ((size_t)(ar < 0 ? 0 : ar) * KDIM + kofs) * 2 + qA0 * 16;
            uint32_t doff = rA0 * 64 + (((uint32_t)(qA0 ^ (rA0 & 3))) << 4);
            cp_async16(base + doff,      (const char*)Ah + so, sz);
            cp_async16(base + PL + doff, (const char*)Al + so, sz);
        }
        {
            int ar = s_map[rA1];
            int sz = ar >= 0 ? 16 : 0;
            size_t so = ((size_t)(ar < 0 ? 0 : ar) * KDIM + kofs) * 2 + qA1 * 16;
            uint32_t doff = rA1 * 64 + (((uint32_t)(qA1 ^ (rA1 & 3))) << 4);
            cp_async16(base + doff,      (const char*)Ah + so, sz);
            cp_async16(base + PL + doff, (const char*)Al + so, sz);
        }
#pragma unroll
        for (int t = 0; t < 2; t++) {
            int idx = tid + t * 256;
            int row = idx >> 2, q = idx & 3;
            int brow = G1 ? (bn0 + (row >> 1) + (row & 1) * F_) : (bn0 + row);
            size_t so = ((size_t)brow * KDIM + kofs) * 2 + q * 16;
            uint32_t doff = row * 64 + (((uint32_t)(q ^ (row & 3))) << 4);
            cp_async16(base + 2 * PL + doff, (const char*)Bh + so, 16);
        }
        cp_commit();
    };

    // warp tile: 64 m x 32 n
    const int wm = (wid >> 2) * 64;
    const int wn = (wid & 3) * 32;
    const int lrow  = lane & 15;
    const int qhalf = lane >> 4;     // 0/1 -> 16B half within k32

    float acc[4][4][4];
#pragma unroll
    for (int i = 0; i < 4; i++)
#pragma unroll
        for (int j = 0; j < 4; j++)
#pragma unroll
            for (int k = 0; k < 4; k++) acc[i][j][k] = 0.f;

    issue(0);
    if (NC > 1) issue(1);

    for (int c = 0; c < NC; c++) {
        if (c + 1 < NC) cp_wait1();
        else            cp_wait0();
        __syncthreads();   // stage c visible; all warps done with stage c-1

        const uint32_t base = dynbase + (uint32_t)(c % NBUF) * BUF;
        const uint32_t ah = base, al = base + PL, bh = base + 2 * PL;

#pragma unroll
        for (int kk = 0; kk < 2; kk++) {
            const int qlog = kk * 2 + qhalf;
            uint32_t bfh[2][4];
#pragma unroll
            for (int g = 0; g < 2; g++) {
                int r = wn + g * 16 + lrow;
                uint32_t ao = (uint32_t)(r * 64 + ((qlog ^ (r & 3)) << 4));
                ldsm4(bfh[g][0], bfh[g][1], bfh[g][2], bfh[g][3], bh + ao);
            }
#pragma unroll
            for (int mi = 0; mi < 4; mi++) {
                int r = wm + mi * 16 + lrow;
                uint32_t ao = (uint32_t)(r * 64 + ((qlog ^ (r & 3)) << 4));
                uint32_t afh[4], afl[4];
                ldsm4(afh[0], afh[1], afh[2], afh[3], ah + ao);
                ldsm4(afl[0], afl[1], afl[2], afl[3], al + ao);
                // product-major: same-acc MMAs 4 issues apart
#pragma unroll
                for (int ni = 0; ni < 4; ni++) {
                    const int g = ni >> 1, sub = ni & 1;
                    mma16816(acc[mi][ni], afh, bfh[g][sub], bfh[g][sub + 2]);
                }
#pragma unroll
                for (int ni = 0; ni < 4; ni++) {
                    const int g = ni >> 1, sub = ni & 1;
                    mma16816(acc[mi][ni], afl, bfh[g][sub], bfh[g][sub + 2]);
                }
            }
        }
        if (c + 2 < NC) issue(c + 2);
    }
    __syncthreads();

    // ---- epilogue (smem reused for staging) ----
    float* stg = (float*)dynraw;
    const int group = lane >> 2;
    const int tig   = lane & 3;

    if (G1) {
#pragma unroll
        for (int mi = 0; mi < 4; mi++) {
            int m = wm + mi * 16 + group;
#pragma unroll
            for (int ni = 0; ni < 4; ni++) {
                int j = (wid & 3) * 16 + ni * 4 + tig;
                float g0 = acc[mi][ni][0], u0 = acc[mi][ni][1];
                float g1 = acc[mi][ni][2], u1 = acc[mi][ni][3];
                stg[m * 68 + j]       = g0 / (1.f + __expf(-g0)) * u0;
                stg[(m + 8) * 68 + j] = g1 / (1.f + __expf(-g1)) * u1;
            }
        }
        __syncthreads();
#pragma unroll
        for (int t = 0; t < 8; t++) {
            int idx = tid + t * 256;
            int row = idx >> 4, q = idx & 15;
            int orow = s_out[row];
            if (orow >= 0) {
                float4 v = *(const float4*)(stg + row * 68 + q * 4);
                uint32_t h0, h1, l0, l1;
                split4h(v, h0, h1, l0, l1);
                size_t ob = ((size_t)orow * F_ + bn0 + q * 4) * 2;
                *(uint2*)((char*)g_act_hi + ob) = make_uint2(h0, h1);
                *(uint2*)((char*)g_act_lo + ob) = make_uint2(l0, l1);
            }
        }
    } else {
        // stage C, then weighted red.global.add into out[tok] (2 contributions
        // per element, fp32 add commutative -> deterministic)
#pragma unroll
        for (int mi = 0; mi < 4; mi++) {
            int m = wm + mi * 16 + group;
#pragma unroll
            for (int ni = 0; ni < 4; ni++) {
                int n = wn + ni * 8 + tig * 2;
                *(float2*)(stg + m * 132 + n)       = make_float2(acc[mi][ni][0], acc[mi][ni][1]);
                *(float2*)(stg + (m + 8) * 132 + n) = make_float2(acc[mi][ni][2], acc[mi][ni][3]);
            }
        }
        __syncthreads();
#pragma unroll
        for (int t = 0; t < 16; t++) {
            int idx = tid + t * 256;
            int row = idx >> 5, q = idx & 31;
            int orow = s_out[row];
            if (orow >= 0) {
                float4 v = *(const float4*)(stg + row * 132 + q * 4);
                float w = s_wt[row];
                float* op = outp + (size_t)(orow >> 1) * D_ + bn0 + q * 4;
                redadd(op + 0, w * v.x);
                redadd(op + 1, w * v.y);
                redadd(op + 2, w * v.z);
                redadd(op + 3, w * v.w);
            }
        }
    }
}

// ---------------- launch ----------------
extern "C" void kernel_launch(void* const* d_in, const int* in_sizes, int n_in,
                              void* d_out, int out_size) {
    const float* x   = (const float*)d_in[0];
    const float* gup = (const float*)d_in[1];
    const float* dwn = (const float*)d_in[2];
    const float* tw  = (const float*)d_in[3];
    const int*   ids = (const int*)d_in[4];
    float* out = (float*)d_out;

    // one-time host-side setup (first call is the non-captured correctness run)
    static bool s_init = false;
    static cudaStream_t s2;
    static cudaEvent_t evF, evJ;
    if (!s_init) {
        cudaFuncSetAttribute(moe_gemm_mma<true>,  cudaFuncAttributeMaxDynamicSharedMemorySize, SMEM_DYN);
        cudaFuncSetAttribute(moe_gemm_mma<false>, cudaFuncAttributeMaxDynamicSharedMemorySize, SMEM_DYN);
        cudaStreamCreateWithFlags(&s2, cudaStreamNonBlocking);
        cudaEventCreateWithFlags(&evF, cudaEventDisableTiming);
        cudaEventCreateWithFlags(&evJ, cudaEventDisableTiming);
        s_init = true;
    }

    // fork: prep_g2 (down split + out zero) overlaps routing + prep_g1 + G1
    cudaEventRecord(evF, 0);
    cudaStreamWaitEvent(s2, evF, 0);
    k_prep_g2<<<(N4_G2 + 255) / 256, 256, 0, s2>>>((const float4*)dwn, (float4*)out);
    cudaEventRecord(evJ, s2);

    k_route<<<1, 1024>>>(ids);
    k_prep_g1<<<(N4_G1 + 255) / 256, 256>>>((const float4*)x, (const float4*)gup);

    moe_gemm_mma<true ><<<dim3(F_ / 64, MAXTILES), 256, SMEM_DYN>>>(tw, out);

    // join: G2 needs down_hi + zeroed out
    cudaStreamWaitEvent(0, evJ, 0);
    moe_gemm_mma<false><<<dim3(D_ / 128, MAXTILES), 256, SMEM_DYN>>>(tw, out);
}